// round 5
// baseline (speedup 1.0000x reference)
#include <cuda_runtime.h>
#include <cstdint>

// Problem constants
#define B_   4
#define C_   256
#define H_   160
#define W_   160
#define HW_  (H_ * W_)          // 25600
#define N_   512
#define PH_  8
#define PW_  64

// 100 MB scratch: features transposed to (B, H*W, C) so channel reads coalesce.
__device__ float g_featT[(size_t)B_ * HW_ * C_];

// ---------------------------------------------------------------------------
// Kernel 1: (B, C, H*W) -> (B, H*W, C) tiled transpose
// grid (HW/32=800, C/32=8, B=4), block (32, 8)
// ---------------------------------------------------------------------------
__global__ void __launch_bounds__(256) transpose_kernel(const float* __restrict__ in)
{
    __shared__ float tile[32][33];

    const int b     = blockIdx.z;
    const int cBase = blockIdx.y * 32;
    const int sBase = blockIdx.x * 32;
    const int tx = threadIdx.x;
    const int ty = threadIdx.y;

    const float* src = in + (size_t)b * C_ * HW_;
#pragma unroll
    for (int j = 0; j < 32; j += 8)
        tile[ty + j][tx] = src[(size_t)(cBase + ty + j) * HW_ + sBase + tx];

    __syncthreads();

    float* dst = g_featT + (size_t)b * HW_ * C_;
#pragma unroll
    for (int j = 0; j < 32; j += 8)
        dst[(size_t)(sBase + ty + j) * C_ + cBase + tx] = tile[tx][ty + j];
}

// ---------------------------------------------------------------------------
// Kernel 2: rotated ROI align on channel-last features.
// One block per (n, py): grid = N*PH = 4096 blocks, 256 threads.
// Phase 1: warp lanes = channels (coalesced LDG.128 of 4 bilinear corners),
//          result stored to a rotation-swizzled smem tile (conflict-free STS.128).
// Phase 2: warp lanes = px (conflict-free LDS.128), coalesced STG.32 writes.
// ---------------------------------------------------------------------------
__global__ void __launch_bounds__(256) rroi_kernel(const float* __restrict__ rois,
                                                   float* __restrict__ out)
{
    __shared__ float4 tile[PW_ * 32];       // 64 px rows x 32 float4 groups = 32 KB
    __shared__ float  s_w[4][PW_];          // bilinear weights per px
    __shared__ int    s_off[4][PW_];        // corner base offsets (in float4 units)

    const int bid = blockIdx.x;
    const int n   = bid >> 3;
    const int py  = bid & 7;
    const int t   = threadIdx.x;

    // ---- per-px sample precompute (threads 0..63) ----
    if (t < PW_) {
        const float* r = rois + n * 6;
        const int   b  = (int)r[0];
        const float cx = r[1];
        const float cy = r[2];
        const float rh = r[3];
        const float rw = r[4];
        const float th = r[5];

        const float sx = rw * (1.0f / PW_);
        const float sy = rh * (1.0f / PH_);
        const float ct = cosf(th);
        const float st = sinf(th);

        const float yy = ((float)py + 0.5f - PH_ * 0.5f) * sy;
        const float xx = ((float)t  + 0.5f - PW_ * 0.5f) * sx;

        const float x = ct * xx + st * yy + cx;
        const float y = -st * xx + ct * yy + cy;

        const float x0f = floorf(x);
        const float y0f = floorf(y);
        const float lx = x - x0f;
        const float ly = y - y0f;
        const int x0 = (int)x0f;
        const int y0 = (int)y0f;
        const int x1 = x0 + 1;
        const int y1 = y0 + 1;

        const bool vx0 = (x0 >= 0) && (x0 < W_);
        const bool vx1 = (x1 >= 0) && (x1 < W_);
        const bool vy0 = (y0 >= 0) && (y0 < H_);
        const bool vy1 = (y1 >= 0) && (y1 < H_);

        const float w00 = (1.0f - lx) * (1.0f - ly) * ((vy0 && vx0) ? 1.0f : 0.0f);
        const float w01 = lx          * (1.0f - ly) * ((vy0 && vx1) ? 1.0f : 0.0f);
        const float w10 = (1.0f - lx) * ly          * ((vy1 && vx0) ? 1.0f : 0.0f);
        const float w11 = lx          * ly          * ((vy1 && vx1) ? 1.0f : 0.0f);

        const int x0c = min(max(x0, 0), W_ - 1);
        const int x1c = min(max(x1, 0), W_ - 1);
        const int y0c = min(max(y0, 0), H_ - 1);
        const int y1c = min(max(y1, 0), H_ - 1);

        const int base = b * HW_;
        // offsets in float4 units: (pos * C_) / 4 = pos * 64
        s_off[0][t] = (base + y0c * W_ + x0c) * (C_ / 4);
        s_off[1][t] = (base + y0c * W_ + x1c) * (C_ / 4);
        s_off[2][t] = (base + y1c * W_ + x0c) * (C_ / 4);
        s_off[3][t] = (base + y1c * W_ + x1c) * (C_ / 4);
        s_w[0][t] = w00;
        s_w[1][t] = w01;
        s_w[2][t] = w10;
        s_w[3][t] = w11;
    }
    __syncthreads();

    const int warp = t >> 5;
    const int lane = t & 31;
    const float4* featT4 = (const float4*)g_featT;

    const unsigned out_base = (unsigned)n * (C_ * PH_ * PW_) + (unsigned)py * PW_;

#pragma unroll
    for (int chunk = 0; chunk < 2; ++chunk) {
        const int c4 = chunk * 32 + lane;   // float4 channel group (global)

        // ---- phase 1: gather + bilinear, lanes = channels ----
#pragma unroll
        for (int i = 0; i < 8; ++i) {
            const int px = warp * 8 + i;
            const float w00 = s_w[0][px];
            const float w01 = s_w[1][px];
            const float w10 = s_w[2][px];
            const float w11 = s_w[3][px];

            const float4 v00 = __ldg(featT4 + s_off[0][px] + c4);
            const float4 v01 = __ldg(featT4 + s_off[1][px] + c4);
            const float4 v10 = __ldg(featT4 + s_off[2][px] + c4);
            const float4 v11 = __ldg(featT4 + s_off[3][px] + c4);

            float4 rv;
            rv.x = w00 * v00.x + w01 * v01.x + w10 * v10.x + w11 * v11.x;
            rv.y = w00 * v00.y + w01 * v01.y + w10 * v10.y + w11 * v11.y;
            rv.z = w00 * v00.z + w01 * v01.z + w10 * v10.z + w11 * v11.z;
            rv.w = w00 * v00.w + w01 * v01.w + w10 * v10.w + w11 * v11.w;

            // rotation swizzle: group g stored at (g + px) & 31 -> conflict-free
            tile[px * 32 + ((lane + px) & 31)] = rv;
        }
        __syncthreads();

        // ---- phase 2: lanes = px, coalesced output writes ----
        const int px    = t & 63;
        const int gbase = t >> 6;   // 0..3
#pragma unroll
        for (int k = 0; k < 8; ++k) {
            const int g = gbase + 4 * k;                 // 0..31
            const float4 v = tile[px * 32 + ((g + px) & 31)];
            const int cglob = chunk * 128 + g * 4;
            const unsigned o = out_base + (unsigned)cglob * (PH_ * PW_) + px;
            out[o]                       = v.x;
            out[o + 1 * PH_ * PW_]       = v.y;
            out[o + 2 * PH_ * PW_]       = v.z;
            out[o + 3 * PH_ * PW_]       = v.w;
        }
        __syncthreads();
    }
}

// ---------------------------------------------------------------------------
extern "C" void kernel_launch(void* const* d_in, const int* in_sizes, int n_in,
                              void* d_out, int out_size)
{
    const float* features = (const float*)d_in[0];
    const float* rois     = (const float*)d_in[1];
    float* out            = (float*)d_out;

    dim3 tgrid(HW_ / 32, C_ / 32, B_);
    dim3 tblk(32, 8);
    transpose_kernel<<<tgrid, tblk>>>(features);

    rroi_kernel<<<N_ * PH_, 256>>>(rois, out);
}

// round 6
// speedup vs baseline: 1.3197x; 1.3197x over previous
#include <cuda_runtime.h>
#include <cuda_fp16.h>
#include <cstdint>

// Problem constants
#define B_   4
#define C_   256
#define H_   160
#define W_   160
#define HW_  (H_ * W_)          // 25600
#define N_   512
#define PH_  8
#define PW_  64

// 50 MB scratch: features transposed to (B, H*W, C) in fp16 so channel reads
// coalesce AND the whole table stays resident in the 126 MB L2.
__device__ __half g_featT[(size_t)B_ * HW_ * C_];

// ---------------------------------------------------------------------------
// Kernel 1: (B, C, H*W) fp32 -> (B, H*W, C) fp16 tiled transpose
// grid (HW/32=800, C/32=8, B=4), block (32, 8)
// ---------------------------------------------------------------------------
__global__ void __launch_bounds__(256) transpose_kernel(const float* __restrict__ in)
{
    __shared__ float tile[32][33];

    const int b     = blockIdx.z;
    const int cBase = blockIdx.y * 32;
    const int sBase = blockIdx.x * 32;
    const int tx = threadIdx.x;
    const int ty = threadIdx.y;

    const float* src = in + (size_t)b * C_ * HW_;
#pragma unroll
    for (int j = 0; j < 32; j += 8)
        tile[ty + j][tx] = __ldcs(&src[(size_t)(cBase + ty + j) * HW_ + sBase + tx]);

    __syncthreads();

    __half* dst = g_featT + (size_t)b * HW_ * C_;
#pragma unroll
    for (int j = 0; j < 32; j += 8)
        dst[(size_t)(sBase + ty + j) * C_ + cBase + tx] = __float2half_rn(tile[tx][ty + j]);
}

// ---------------------------------------------------------------------------
// Kernel 2: rotated ROI align on channel-last fp16 features.
// One block per (n, py): grid = N*PH = 4096 blocks, 256 threads.
// Phase 1: warp lanes = channel groups (coalesced LDG.64 of 4 bilinear
//          corners, fp16 -> fp32), results in rotation-swizzled smem tile.
// Phase 2: warp lanes = px (conflict-free LDS.128), coalesced streaming
//          STG.32 writes (bypass L2 allocate to protect featT residency).
// ---------------------------------------------------------------------------
__global__ void __launch_bounds__(256, 6) rroi_kernel(const float* __restrict__ rois,
                                                      float* __restrict__ out)
{
    __shared__ float4 tile[PW_ * 32];       // 64 px rows x 32 float4 groups = 32 KB
    __shared__ float  s_w[4][PW_];          // bilinear weights per px
    __shared__ int    s_off[4][PW_];        // corner base offsets (in uint2 = 4-half units)

    const int bid = blockIdx.x;
    const int n   = bid >> 3;
    const int py  = bid & 7;
    const int t   = threadIdx.x;

    // ---- per-px sample precompute (threads 0..63) ----
    if (t < PW_) {
        const float* r = rois + n * 6;
        const int   b  = (int)r[0];
        const float cx = r[1];
        const float cy = r[2];
        const float rh = r[3];
        const float rw = r[4];
        const float th = r[5];

        const float sx = rw * (1.0f / PW_);
        const float sy = rh * (1.0f / PH_);
        const float ct = cosf(th);
        const float st = sinf(th);

        const float yy = ((float)py + 0.5f - PH_ * 0.5f) * sy;
        const float xx = ((float)t  + 0.5f - PW_ * 0.5f) * sx;

        const float x = ct * xx + st * yy + cx;
        const float y = -st * xx + ct * yy + cy;

        const float x0f = floorf(x);
        const float y0f = floorf(y);
        const float lx = x - x0f;
        const float ly = y - y0f;
        const int x0 = (int)x0f;
        const int y0 = (int)y0f;
        const int x1 = x0 + 1;
        const int y1 = y0 + 1;

        const bool vx0 = (x0 >= 0) && (x0 < W_);
        const bool vx1 = (x1 >= 0) && (x1 < W_);
        const bool vy0 = (y0 >= 0) && (y0 < H_);
        const bool vy1 = (y1 >= 0) && (y1 < H_);

        const float w00 = (1.0f - lx) * (1.0f - ly) * ((vy0 && vx0) ? 1.0f : 0.0f);
        const float w01 = lx          * (1.0f - ly) * ((vy0 && vx1) ? 1.0f : 0.0f);
        const float w10 = (1.0f - lx) * ly          * ((vy1 && vx0) ? 1.0f : 0.0f);
        const float w11 = lx          * ly          * ((vy1 && vx1) ? 1.0f : 0.0f);

        const int x0c = min(max(x0, 0), W_ - 1);
        const int x1c = min(max(x1, 0), W_ - 1);
        const int y0c = min(max(y0, 0), H_ - 1);
        const int y1c = min(max(y1, 0), H_ - 1);

        const int base = b * HW_;
        // offsets in uint2 units (4 halfs): pos * C_ / 4 = pos * 64
        s_off[0][t] = (base + y0c * W_ + x0c) * (C_ / 4);
        s_off[1][t] = (base + y0c * W_ + x1c) * (C_ / 4);
        s_off[2][t] = (base + y1c * W_ + x0c) * (C_ / 4);
        s_off[3][t] = (base + y1c * W_ + x1c) * (C_ / 4);
        s_w[0][t] = w00;
        s_w[1][t] = w01;
        s_w[2][t] = w10;
        s_w[3][t] = w11;
    }
    __syncthreads();

    const int warp = t >> 5;
    const int lane = t & 31;
    const uint2* featH = (const uint2*)g_featT;   // one uint2 = 4 fp16 channels

    const unsigned out_base = (unsigned)n * (C_ * PH_ * PW_) + (unsigned)py * PW_;

#pragma unroll
    for (int chunk = 0; chunk < 2; ++chunk) {
        const int c4 = chunk * 32 + lane;   // 4-channel group (global)

        // ---- phase 1: gather + bilinear, lanes = channel groups ----
#pragma unroll
        for (int i = 0; i < 8; ++i) {
            const int px = warp * 8 + i;
            const float w00 = s_w[0][px];
            const float w01 = s_w[1][px];
            const float w10 = s_w[2][px];
            const float w11 = s_w[3][px];

            const uint2 r00 = __ldg(featH + s_off[0][px] + c4);
            const uint2 r01 = __ldg(featH + s_off[1][px] + c4);
            const uint2 r10 = __ldg(featH + s_off[2][px] + c4);
            const uint2 r11 = __ldg(featH + s_off[3][px] + c4);

            const float2 a00 = __half22float2(*(const __half2*)&r00.x);
            const float2 b00 = __half22float2(*(const __half2*)&r00.y);
            const float2 a01 = __half22float2(*(const __half2*)&r01.x);
            const float2 b01 = __half22float2(*(const __half2*)&r01.y);
            const float2 a10 = __half22float2(*(const __half2*)&r10.x);
            const float2 b10 = __half22float2(*(const __half2*)&r10.y);
            const float2 a11 = __half22float2(*(const __half2*)&r11.x);
            const float2 b11 = __half22float2(*(const __half2*)&r11.y);

            float4 rv;
            rv.x = w00 * a00.x + w01 * a01.x + w10 * a10.x + w11 * a11.x;
            rv.y = w00 * a00.y + w01 * a01.y + w10 * a10.y + w11 * a11.y;
            rv.z = w00 * b00.x + w01 * b01.x + w10 * b10.x + w11 * b11.x;
            rv.w = w00 * b00.y + w01 * b01.y + w10 * b10.y + w11 * b11.y;

            // rotation swizzle: group g stored at (g + px) & 31 -> conflict-free
            tile[px * 32 + ((lane + px) & 31)] = rv;
        }
        __syncthreads();

        // ---- phase 2: lanes = px, coalesced streaming output writes ----
        const int px    = t & 63;
        const int gbase = t >> 6;   // 0..3
#pragma unroll
        for (int k = 0; k < 8; ++k) {
            const int g = gbase + 4 * k;                 // 0..31
            const float4 v = tile[px * 32 + ((g + px) & 31)];
            const int cglob = chunk * 128 + g * 4;
            const unsigned o = out_base + (unsigned)cglob * (PH_ * PW_) + px;
            __stcs(out + o,                 v.x);
            __stcs(out + o + 1 * PH_ * PW_, v.y);
            __stcs(out + o + 2 * PH_ * PW_, v.z);
            __stcs(out + o + 3 * PH_ * PW_, v.w);
        }
        __syncthreads();
    }
}

// ---------------------------------------------------------------------------
extern "C" void kernel_launch(void* const* d_in, const int* in_sizes, int n_in,
                              void* d_out, int out_size)
{
    const float* features = (const float*)d_in[0];
    const float* rois     = (const float*)d_in[1];
    float* out            = (float*)d_out;

    dim3 tgrid(HW_ / 32, C_ / 32, B_);
    dim3 tblk(32, 8);
    transpose_kernel<<<tgrid, tblk>>>(features);

    rroi_kernel<<<N_ * PH_, 256>>>(rois, out);
}

// round 7
// speedup vs baseline: 1.5457x; 1.1713x over previous
#include <cuda_runtime.h>
#include <cuda_fp16.h>
#include <cstdint>

// Problem constants
#define B_   4
#define C_   256
#define H_   160
#define W_   160
#define HW_  (H_ * W_)          // 25600
#define N_   512
#define PH_  8
#define PW_  64

// 50 MB scratch: features transposed to (B, H*W, C) in fp16 so channel reads
// coalesce AND the whole table stays resident in the 126 MB L2.
__device__ __half g_featT[(size_t)B_ * HW_ * C_];

// ---------------------------------------------------------------------------
// Kernel 1: (B, C, H*W) fp32 -> (B, H*W, C) fp16 tiled transpose.
// 64-channel x 32-spatial tiles so fp16 writes are full 128B wavefronts
// (warp writes 32 x half2 contiguous in one spatial row).
// grid (HW/32=800, C/64=4, B=4), block (32, 8)
// ---------------------------------------------------------------------------
__global__ void __launch_bounds__(256) transpose_kernel(const float* __restrict__ in)
{
    __shared__ float tile[64][33];

    const int b     = blockIdx.z;
    const int cBase = blockIdx.y * 64;
    const int sBase = blockIdx.x * 32;
    const int tx = threadIdx.x;
    const int ty = threadIdx.y;

    const float* src = in + (size_t)b * C_ * HW_;
#pragma unroll
    for (int j = 0; j < 64; j += 8)
        tile[ty + j][tx] = __ldcs(&src[(size_t)(cBase + ty + j) * HW_ + sBase + tx]);

    __syncthreads();

    // Write: warp ty handles spatial rows ty, ty+8, ty+16, ty+24.
    // Lane tx packs channels (2*tx, 2*tx+1) into one half2 -> 128B per warp store.
    __half2* dst2 = (__half2*)(g_featT + (size_t)b * HW_ * C_);
#pragma unroll
    for (int m = 0; m < 4; ++m) {
        const int s = ty + 8 * m;
        const float lo = tile[2 * tx][s];
        const float hi = tile[2 * tx + 1][s];
        dst2[((size_t)(sBase + s) * C_ + cBase) / 2 + tx] = __floats2half2_rn(lo, hi);
    }
}

// ---------------------------------------------------------------------------
// Kernel 2: rotated ROI align on channel-last fp16 features.
// One block per (n, py): grid = N*PH = 4096 blocks, 256 threads.
// Phase 1: warp lanes = 8-channel groups; one LDG.128 per corner covers all
//          256 channels warp-wide. fp32 interpolation, result packed to fp16
//          in a rotation-swizzled smem tile (halves smem traffic vs fp32).
// Phase 2: lanes = px; conflict-free LDS.128, coalesced streaming STG.32.
// ---------------------------------------------------------------------------
__global__ void __launch_bounds__(256, 6) rroi_kernel(const float* __restrict__ rois,
                                                      float* __restrict__ out)
{
    __shared__ uint4 tile[PW_ * 32];        // 64 px x 32 groups x 8 fp16 ch = 32 KB
    __shared__ float s_w[4][PW_];           // bilinear weights per px
    __shared__ int   s_off[4][PW_];         // corner base offsets (uint4 = 8-half units)

    const int bid = blockIdx.x;
    const int n   = bid >> 3;
    const int py  = bid & 7;
    const int t   = threadIdx.x;

    // ---- per-px sample precompute (threads 0..63) ----
    if (t < PW_) {
        const float* r = rois + n * 6;
        const int   b  = (int)r[0];
        const float cx = r[1];
        const float cy = r[2];
        const float rh = r[3];
        const float rw = r[4];
        const float th = r[5];

        const float sx = rw * (1.0f / PW_);
        const float sy = rh * (1.0f / PH_);
        const float ct = cosf(th);
        const float st = sinf(th);

        const float yy = ((float)py + 0.5f - PH_ * 0.5f) * sy;
        const float xx = ((float)t  + 0.5f - PW_ * 0.5f) * sx;

        const float x = ct * xx + st * yy + cx;
        const float y = -st * xx + ct * yy + cy;

        const float x0f = floorf(x);
        const float y0f = floorf(y);
        const float lx = x - x0f;
        const float ly = y - y0f;
        const int x0 = (int)x0f;
        const int y0 = (int)y0f;
        const int x1 = x0 + 1;
        const int y1 = y0 + 1;

        const bool vx0 = (x0 >= 0) && (x0 < W_);
        const bool vx1 = (x1 >= 0) && (x1 < W_);
        const bool vy0 = (y0 >= 0) && (y0 < H_);
        const bool vy1 = (y1 >= 0) && (y1 < H_);

        const float w00 = (1.0f - lx) * (1.0f - ly) * ((vy0 && vx0) ? 1.0f : 0.0f);
        const float w01 = lx          * (1.0f - ly) * ((vy0 && vx1) ? 1.0f : 0.0f);
        const float w10 = (1.0f - lx) * ly          * ((vy1 && vx0) ? 1.0f : 0.0f);
        const float w11 = lx          * ly          * ((vy1 && vx1) ? 1.0f : 0.0f);

        const int x0c = min(max(x0, 0), W_ - 1);
        const int x1c = min(max(x1, 0), W_ - 1);
        const int y0c = min(max(y0, 0), H_ - 1);
        const int y1c = min(max(y1, 0), H_ - 1);

        const int base = b * HW_;
        // offsets in uint4 units (8 halfs): pos * C_ / 8 = pos * 32
        s_off[0][t] = (base + y0c * W_ + x0c) * (C_ / 8);
        s_off[1][t] = (base + y0c * W_ + x1c) * (C_ / 8);
        s_off[2][t] = (base + y1c * W_ + x0c) * (C_ / 8);
        s_off[3][t] = (base + y1c * W_ + x1c) * (C_ / 8);
        s_w[0][t] = w00;
        s_w[1][t] = w01;
        s_w[2][t] = w10;
        s_w[3][t] = w11;
    }
    __syncthreads();

    const int warp = t >> 5;
    const int lane = t & 31;
    const uint4* featU = (const uint4*)g_featT;   // one uint4 = 8 fp16 channels

    // ---- phase 1: gather + bilinear, lanes = 8-channel groups ----
#pragma unroll
    for (int i = 0; i < 8; ++i) {
        const int px = warp * 8 + i;
        const float w00 = s_w[0][px];
        const float w01 = s_w[1][px];
        const float w10 = s_w[2][px];
        const float w11 = s_w[3][px];

        const uint4 r00 = __ldg(featU + s_off[0][px] + lane);
        const uint4 r01 = __ldg(featU + s_off[1][px] + lane);
        const uint4 r10 = __ldg(featU + s_off[2][px] + lane);
        const uint4 r11 = __ldg(featU + s_off[3][px] + lane);

        float acc[8];
#pragma unroll
        for (int q = 0; q < 4; ++q) {
            const float2 a = __half22float2(*(((const __half2*)&r00) + q));
            const float2 b = __half22float2(*(((const __half2*)&r01) + q));
            const float2 c = __half22float2(*(((const __half2*)&r10) + q));
            const float2 d = __half22float2(*(((const __half2*)&r11) + q));
            acc[2 * q]     = w00 * a.x + w01 * b.x + w10 * c.x + w11 * d.x;
            acc[2 * q + 1] = w00 * a.y + w01 * b.y + w10 * c.y + w11 * d.y;
        }

        uint4 packed;
        ((__half2*)&packed)[0] = __floats2half2_rn(acc[0], acc[1]);
        ((__half2*)&packed)[1] = __floats2half2_rn(acc[2], acc[3]);
        ((__half2*)&packed)[2] = __floats2half2_rn(acc[4], acc[5]);
        ((__half2*)&packed)[3] = __floats2half2_rn(acc[6], acc[7]);

        // rotation swizzle: group g stored at (g + px) & 31 -> conflict-free
        tile[px * 32 + ((lane + px) & 31)] = packed;
    }
    __syncthreads();

    // ---- phase 2: lanes = px, coalesced streaming output writes ----
    const unsigned out_base = (unsigned)n * (C_ * PH_ * PW_) + (unsigned)py * PW_;
    const int px    = t & 63;
    const int gbase = t >> 6;   // 0..3
#pragma unroll
    for (int k = 0; k < 8; ++k) {
        const int g = gbase + 4 * k;                 // 0..31
        const uint4 v = tile[px * 32 + ((g + px) & 31)];
        const int cglob = g * 8;
        const unsigned o = out_base + (unsigned)cglob * (PH_ * PW_) + px;
#pragma unroll
        for (int q = 0; q < 4; ++q) {
            const float2 f = __half22float2(*(((const __half2*)&v) + q));
            __stcs(out + o + (2 * q)     * (PH_ * PW_), f.x);
            __stcs(out + o + (2 * q + 1) * (PH_ * PW_), f.y);
        }
    }
}

// ---------------------------------------------------------------------------
extern "C" void kernel_launch(void* const* d_in, const int* in_sizes, int n_in,
                              void* d_out, int out_size)
{
    const float* features = (const float*)d_in[0];
    const float* rois     = (const float*)d_in[1];
    float* out            = (float*)d_out;

    dim3 tgrid(HW_ / 32, C_ / 64, B_);
    dim3 tblk(32, 8);
    transpose_kernel<<<tgrid, tblk>>>(features);

    rroi_kernel<<<N_ * PH_, 256>>>(rois, out);
}

// round 8
// speedup vs baseline: 1.6336x; 1.0569x over previous
#include <cuda_runtime.h>
#include <cuda_fp16.h>
#include <cstdint>

// Problem constants
#define B_   4
#define C_   256
#define H_   160
#define W_   160
#define HW_  (H_ * W_)          // 25600
#define N_   512
#define PH_  8
#define PW_  64

// 50 MB scratch: features transposed to (B, H*W, C) in fp16 so channel reads
// coalesce AND the whole table stays resident in the 126 MB L2.
__device__ __half g_featT[(size_t)B_ * HW_ * C_];

// ---------------------------------------------------------------------------
// Kernel 1: (B, C, H*W) fp32 -> (B, H*W, C) fp16 tiled transpose.
// 64-channel x 32-spatial tiles so fp16 writes are full 128B wavefronts.
// grid (HW/32=800, C/64=4, B=4), block (32, 8)
// ---------------------------------------------------------------------------
__global__ void __launch_bounds__(256) transpose_kernel(const float* __restrict__ in)
{
    __shared__ float tile[64][33];

    const int b     = blockIdx.z;
    const int cBase = blockIdx.y * 64;
    const int sBase = blockIdx.x * 32;
    const int tx = threadIdx.x;
    const int ty = threadIdx.y;

    const float* src = in + (size_t)b * C_ * HW_;
#pragma unroll
    for (int j = 0; j < 64; j += 8)
        tile[ty + j][tx] = __ldcs(&src[(size_t)(cBase + ty + j) * HW_ + sBase + tx]);

    __syncthreads();

    __half2* dst2 = (__half2*)(g_featT + (size_t)b * HW_ * C_);
#pragma unroll
    for (int m = 0; m < 4; ++m) {
        const int s = ty + 8 * m;
        const float lo = tile[2 * tx][s];
        const float hi = tile[2 * tx + 1][s];
        dst2[((size_t)(sBase + s) * C_ + cBase) / 2 + tx] = __floats2half2_rn(lo, hi);
    }
}

// ---------------------------------------------------------------------------
// Kernel 2: rotated ROI align on channel-last fp16 features.
// One block per (n, py): grid = N*PH = 4096 blocks, 256 threads.
// Phase 1: 4 iterations x px-PAIR per warp -> 8 independent LDG.128 in flight
//          per iteration (double MLP vs single-px). fp32 math, fp16 tile.
// Phase 2: lanes = px pairs; conflict-free LDS.128, coalesced streaming STG.64.
// Swizzle rotation keyed on (px>>1) so both rows of a pair share a rotation.
// ---------------------------------------------------------------------------
__global__ void __launch_bounds__(256, 5) rroi_kernel(const float* __restrict__ rois,
                                                      float* __restrict__ out)
{
    __shared__ uint4  tile[PW_ * 32];       // 64 px x 32 groups x 8 fp16 ch = 32 KB
    __shared__ float4 s_w4[PW_];            // bilinear weights per px
    __shared__ int4   s_off4[PW_];          // corner base offsets (uint4 = 8-half units)

    const int bid = blockIdx.x;
    const int n   = bid >> 3;
    const int py  = bid & 7;
    const int t   = threadIdx.x;

    // ---- per-px sample precompute (threads 0..63) ----
    if (t < PW_) {
        const float* r = rois + n * 6;
        const int   b  = (int)r[0];
        const float cx = r[1];
        const float cy = r[2];
        const float rh = r[3];
        const float rw = r[4];
        const float th = r[5];

        const float sx = rw * (1.0f / PW_);
        const float sy = rh * (1.0f / PH_);
        const float ct = cosf(th);
        const float st = sinf(th);

        const float yy = ((float)py + 0.5f - PH_ * 0.5f) * sy;
        const float xx = ((float)t  + 0.5f - PW_ * 0.5f) * sx;

        const float x = ct * xx + st * yy + cx;
        const float y = -st * xx + ct * yy + cy;

        const float x0f = floorf(x);
        const float y0f = floorf(y);
        const float lx = x - x0f;
        const float ly = y - y0f;
        const int x0 = (int)x0f;
        const int y0 = (int)y0f;
        const int x1 = x0 + 1;
        const int y1 = y0 + 1;

        const bool vx0 = (x0 >= 0) && (x0 < W_);
        const bool vx1 = (x1 >= 0) && (x1 < W_);
        const bool vy0 = (y0 >= 0) && (y0 < H_);
        const bool vy1 = (y1 >= 0) && (y1 < H_);

        float4 wv;
        wv.x = (1.0f - lx) * (1.0f - ly) * ((vy0 && vx0) ? 1.0f : 0.0f);
        wv.y = lx          * (1.0f - ly) * ((vy0 && vx1) ? 1.0f : 0.0f);
        wv.z = (1.0f - lx) * ly          * ((vy1 && vx0) ? 1.0f : 0.0f);
        wv.w = lx          * ly          * ((vy1 && vx1) ? 1.0f : 0.0f);

        const int x0c = min(max(x0, 0), W_ - 1);
        const int x1c = min(max(x1, 0), W_ - 1);
        const int y0c = min(max(y0, 0), H_ - 1);
        const int y1c = min(max(y1, 0), H_ - 1);

        const int base = b * HW_;
        int4 ov;   // offsets in uint4 units (8 halfs): pos * C_/8 = pos * 32
        ov.x = (base + y0c * W_ + x0c) * (C_ / 8);
        ov.y = (base + y0c * W_ + x1c) * (C_ / 8);
        ov.z = (base + y1c * W_ + x0c) * (C_ / 8);
        ov.w = (base + y1c * W_ + x1c) * (C_ / 8);

        s_w4[t]   = wv;
        s_off4[t] = ov;
    }
    __syncthreads();

    const int warp = t >> 5;
    const int lane = t & 31;
    const uint4* featU = (const uint4*)g_featT;   // one uint4 = 8 fp16 channels

    // ---- phase 1: gather + bilinear, px pairs for doubled MLP ----
#pragma unroll
    for (int i = 0; i < 4; ++i) {
        const int px0 = warp * 8 + 2 * i;
        const int px1 = px0 + 1;
        const int rot = px0 >> 1;           // shared rotation for the pair
        const int col = (lane + rot) & 31;

        const float4 wA = s_w4[px0];
        const float4 wB = s_w4[px1];
        const int4   oA = s_off4[px0];
        const int4   oB = s_off4[px1];

        // 8 independent 128-bit gathers
        const uint4 a00 = __ldg(featU + oA.x + lane);
        const uint4 a01 = __ldg(featU + oA.y + lane);
        const uint4 a10 = __ldg(featU + oA.z + lane);
        const uint4 a11 = __ldg(featU + oA.w + lane);
        const uint4 b00 = __ldg(featU + oB.x + lane);
        const uint4 b01 = __ldg(featU + oB.y + lane);
        const uint4 b10 = __ldg(featU + oB.z + lane);
        const uint4 b11 = __ldg(featU + oB.w + lane);

        uint4 packedA, packedB;
#pragma unroll
        for (int q = 0; q < 4; ++q) {
            const float2 pa = __half22float2(((const __half2*)&a00)[q]);
            const float2 pb = __half22float2(((const __half2*)&a01)[q]);
            const float2 pc = __half22float2(((const __half2*)&a10)[q]);
            const float2 pd = __half22float2(((const __half2*)&a11)[q]);
            const float ax = wA.x * pa.x + wA.y * pb.x + wA.z * pc.x + wA.w * pd.x;
            const float ay = wA.x * pa.y + wA.y * pb.y + wA.z * pc.y + wA.w * pd.y;
            ((__half2*)&packedA)[q] = __floats2half2_rn(ax, ay);
        }
#pragma unroll
        for (int q = 0; q < 4; ++q) {
            const float2 pa = __half22float2(((const __half2*)&b00)[q]);
            const float2 pb = __half22float2(((const __half2*)&b01)[q]);
            const float2 pc = __half22float2(((const __half2*)&b10)[q]);
            const float2 pd = __half22float2(((const __half2*)&b11)[q]);
            const float bx = wB.x * pa.x + wB.y * pb.x + wB.z * pc.x + wB.w * pd.x;
            const float by = wB.x * pa.y + wB.y * pb.y + wB.z * pc.y + wB.w * pd.y;
            ((__half2*)&packedB)[q] = __floats2half2_rn(bx, by);
        }

        tile[px0 * 32 + col] = packedA;
        tile[px1 * 32 + col] = packedB;
    }
    __syncthreads();

    // ---- phase 2: lanes = px pairs, coalesced streaming STG.64 ----
    const unsigned out_base = (unsigned)n * (C_ * PH_ * PW_) + (unsigned)py * PW_;
    const int pp = t & 31;      // px pair index: px {2pp, 2pp+1}
    const int gb = t >> 5;      // 0..7
#pragma unroll
    for (int k = 0; k < 4; ++k) {
        const int g   = gb * 4 + k;                  // 0..31
        const int col = (g + pp) & 31;               // rotation = px>>1 = pp
        const uint4 v0 = tile[(2 * pp)     * 32 + col];
        const uint4 v1 = tile[(2 * pp + 1) * 32 + col];
        const int cbase = g * 8;
        const unsigned o0 = out_base + (unsigned)cbase * (PH_ * PW_) + 2 * pp;
#pragma unroll
        for (int q = 0; q < 4; ++q) {
            const float2 f0 = __half22float2(((const __half2*)&v0)[q]);
            const float2 f1 = __half22float2(((const __half2*)&v1)[q]);
            // channel cbase+2q: px pair values; channel cbase+2q+1 likewise
            const float2 sA = make_float2(f0.x, f1.x);
            const float2 sB = make_float2(f0.y, f1.y);
            __stcs((float2*)(out + o0 + (2 * q)     * (PH_ * PW_)), sA);
            __stcs((float2*)(out + o0 + (2 * q + 1) * (PH_ * PW_)), sB);
        }
    }
}

// ---------------------------------------------------------------------------
extern "C" void kernel_launch(void* const* d_in, const int* in_sizes, int n_in,
                              void* d_out, int out_size)
{
    const float* features = (const float*)d_in[0];
    const float* rois     = (const float*)d_in[1];
    float* out            = (float*)d_out;

    dim3 tgrid(HW_ / 32, C_ / 64, B_);
    dim3 tblk(32, 8);
    transpose_kernel<<<tgrid, tblk>>>(features);

    rroi_kernel<<<N_ * PH_, 256>>>(rois, out);
}